// round 1
// baseline (speedup 1.0000x reference)
#include <cuda_runtime.h>
#include <cstdint>

// ---------------------------------------------------------------------------
// Problem constants
// ---------------------------------------------------------------------------
#define BATCH   256
#define C_IN    4
#define LIN     2048
#define HNODE   256
#define GLEN    24
#define LOUT    2025          // LIN - GLEN + 1
#define TWOH    512           // 2*HNODE

// ---------------------------------------------------------------------------
// Device scratch (no allocations allowed)
// ---------------------------------------------------------------------------
__device__ ulonglong2 g_wInt[HNODE * GLEN];        // weights interleaved: (h,g) -> {c0,c1 | c2,c3}
__device__ float      g_pool[BATCH * TWOH];        // [max(256) | avg(256)] per batch

// ---------------------------------------------------------------------------
// Helpers: packed f32x2 math (FFMA2 — full-rate fp32 on sm_103a)
// ---------------------------------------------------------------------------
__device__ __forceinline__ unsigned long long ffma2(unsigned long long a,
                                                    unsigned long long b,
                                                    unsigned long long c) {
    unsigned long long d;
    asm("fma.rn.f32x2 %0, %1, %2, %3;" : "=l"(d) : "l"(a), "l"(b), "l"(c));
    return d;
}
__device__ __forceinline__ unsigned long long pk2(float lo, float hi) {
    return (unsigned long long)__float_as_uint(lo) |
           ((unsigned long long)__float_as_uint(hi) << 32);
}
__device__ __forceinline__ float flo(unsigned long long u) {
    return __uint_as_float((unsigned)(u & 0xffffffffull));
}
__device__ __forceinline__ float fhi(unsigned long long u) {
    return __uint_as_float((unsigned)(u >> 32));
}

// ---------------------------------------------------------------------------
// Kernel 0: interleave conv weights  wConv[h][c][g] -> g_wInt[h*24+g] = {c0,c1,c2,c3}
// ---------------------------------------------------------------------------
__global__ void prep_w_kernel(const float* __restrict__ wConv) {
    int id = blockIdx.x * blockDim.x + threadIdx.x;
    if (id < HNODE * GLEN) {
        int h = id / GLEN, g = id % GLEN;
        const float* wb = wConv + h * (C_IN * GLEN);
        ulonglong2 v;
        v.x = pk2(wb[0 * GLEN + g], wb[1 * GLEN + g]);
        v.y = pk2(wb[2 * GLEN + g], wb[3 * GLEN + g]);
        g_wInt[id] = v;
    }
}

// ---------------------------------------------------------------------------
// Kernel 1: fused conv1d + bias + relu + max/avg pool
// Grid: 1024 CTAs = (batch b, h-quarter hq). 256 threads.
// Thread -> (h = hq*64 + tid>>2, l-quarter lq = tid&3).
// Weights in registers, x interleaved in smem, packed f32x2 FMAs.
// ---------------------------------------------------------------------------
__global__ void __launch_bounds__(256)
conv_pool_kernel(const float* __restrict__ x, const float* __restrict__ wRect) {
    __shared__ ulonglong2 xs[LIN + 32];   // padded so window reads never go OOB

    const int b   = blockIdx.x >> 2;
    const int hq  = blockIdx.x & 3;
    const int tid = threadIdx.x;

    // ---- stage x[b] interleaved into smem: xs[l] = {x0(l),x1(l) | x2(l),x3(l)} ----
    const float* xb = x + (size_t)b * C_IN * LIN;
    for (int l = tid; l < LIN + 32; l += 256) {
        ulonglong2 v;
        if (l < LIN) {
            v.x = pk2(xb[l], xb[LIN + l]);
            v.y = pk2(xb[2 * LIN + l], xb[3 * LIN + l]);
        } else {
            v.x = 0ull; v.y = 0ull;
        }
        xs[l] = v;
    }

    const int h  = hq * 64 + (tid >> 2);
    const int lq = tid & 3;

    // ---- weights for this thread's filter: 24 x {c01,c23} in registers ----
    ulonglong2 w[GLEN];
#pragma unroll
    for (int g = 0; g < GLEN; ++g) w[g] = g_wInt[h * GLEN + g];
    const float rb = wRect[h];

    __syncthreads();

    const int l0 = (lq * LOUT) >> 2;
    const int l1 = ((lq + 1) * LOUT) >> 2;

    float m = 0.0f;   // rect >= 0, so 0 is a valid max identity
    float s = 0.0f;

    for (int l = l0; l < l1; l += 2) {
        unsigned long long a0, a1, b0, b1;
        {   // p = 0: contributes to position l only
            ulonglong2 xv = xs[l];
            a0 = ffma2(w[0].x, xv.x, 0ull);
            a1 = ffma2(w[0].y, xv.y, 0ull);
            b0 = 0ull; b1 = 0ull;
        }
#pragma unroll
        for (int p = 1; p < GLEN; ++p) {   // shared loads serve both positions
            ulonglong2 xv = xs[l + p];
            a0 = ffma2(w[p].x,     xv.x, a0);
            a1 = ffma2(w[p].y,     xv.y, a1);
            b0 = ffma2(w[p - 1].x, xv.x, b0);
            b1 = ffma2(w[p - 1].y, xv.y, b1);
        }
        {   // p = 24: contributes to position l+1 only
            ulonglong2 xv = xs[l + GLEN];
            b0 = ffma2(w[GLEN - 1].x, xv.x, b0);
            b1 = ffma2(w[GLEN - 1].y, xv.y, b1);
        }

        float c0 = (flo(a0) + fhi(a0)) + (flo(a1) + fhi(a1)) + rb;
        float r0 = fmaxf(c0, 0.0f);
        m = fmaxf(m, r0); s += r0;

        if (l + 1 < l1) {
            float c1 = (flo(b0) + fhi(b0)) + (flo(b1) + fhi(b1)) + rb;
            float r1 = fmaxf(c1, 0.0f);
            m = fmaxf(m, r1); s += r1;
        }
    }

    // combine the 4 l-quarter lanes that share h (lanes tid..tid^3)
    m = fmaxf(m, __shfl_xor_sync(0xffffffffu, m, 1));
    s +=        __shfl_xor_sync(0xffffffffu, s, 1);
    m = fmaxf(m, __shfl_xor_sync(0xffffffffu, m, 2));
    s +=        __shfl_xor_sync(0xffffffffu, s, 2);

    if (lq == 0) {
        g_pool[b * TWOH + h]         = m;                     // maxPool
        g_pool[b * TWOH + HNODE + h] = s * (1.0f / LOUT);     // avgPool
    }
}

// ---------------------------------------------------------------------------
// Kernel 2: MLP head.  hid = relu(pool @ wHidden + bHid);
//           out = 0.5 * (hid @ wNeu) + bNeu.  One CTA per batch row.
// ---------------------------------------------------------------------------
__global__ void __launch_bounds__(TWOH)
mlp_kernel(const float* __restrict__ wH, const float* __restrict__ wHB,
           const float* __restrict__ wNeu, const float* __restrict__ wNB,
           float* __restrict__ out) {
    __shared__ float prow[TWOH];
    __shared__ float red[TWOH];
    const int b = blockIdx.x, tid = threadIdx.x;

    prow[tid] = g_pool[b * TWOH + tid];
    __syncthreads();

    float acc = 0.0f;
#pragma unroll 8
    for (int i = 0; i < TWOH; ++i)
        acc = fmaf(prow[i], wH[i * TWOH + tid], acc);   // coalesced over tid

    float hid = fmaxf(acc + wHB[tid], 0.0f);
    red[tid] = hid * wNeu[tid];
    __syncthreads();

#pragma unroll
    for (int st = TWOH / 2; st > 0; st >>= 1) {
        if (tid < st) red[tid] += red[tid + st];
        __syncthreads();
    }
    if (tid == 0) out[b] = 0.5f * red[0] + wNB[0];
}

// ---------------------------------------------------------------------------
// Launch
// ---------------------------------------------------------------------------
extern "C" void kernel_launch(void* const* d_in, const int* in_sizes, int n_in,
                              void* d_out, int out_size) {
    const float* x     = (const float*)d_in[0];
    const float* wConv = (const float*)d_in[1];
    const float* wRect = (const float*)d_in[2];
    const float* wH    = (const float*)d_in[3];
    const float* wHB   = (const float*)d_in[4];
    const float* wNeu  = (const float*)d_in[5];
    const float* wNB   = (const float*)d_in[6];
    float* out = (float*)d_out;

    prep_w_kernel<<<(HNODE * GLEN + 255) / 256, 256>>>(wConv);
    conv_pool_kernel<<<BATCH * 4, 256>>>(x, wRect);
    mlp_kernel<<<BATCH, TWOH>>>(wH, wHB, wNeu, wNB, out);
}

// round 3
// speedup vs baseline: 2.7018x; 2.7018x over previous
#include <cuda_runtime.h>
#include <cuda_bf16.h>
#include <cstdint>

// ---------------------------------------------------------------------------
// Problem constants
// ---------------------------------------------------------------------------
#define BATCH  256
#define LIN    2048
#define HNODE  256
#define GLEN   24
#define LOUT   2025
#define TWOH   512
#define KDIM   96           // 4 channels * 24 taps, k = 4*g + c
#define NTILES 16           // 16 * 128 l-positions
#define XPAD   2080         // max Xi read = 15*128+127+23 = 2070
#define BPITCH 104          // bf16 per B row (208 B) -> conflict-free frag LDS

// ---------------------------------------------------------------------------
// Dynamic shared memory layout (bytes)
// ---------------------------------------------------------------------------
#define OFF_XI_H 0                       // 2080 * 8 = 16640
#define OFF_XI_L 16640                   // 16640
#define OFF_BH   33280                   // 128 * 208 = 26624
#define OFF_BL   59904                   // 26624 -> 86528
#define OFF_WF   33280                   // prologue-only overlay (128*96*4 = 49152 < 53248)
#define OFF_RED  33280                   // post-loop overlay: 1024 floats
#define SMEM_BYTES 86528

__device__ float g_pool[BATCH * TWOH];   // [max(256) | avg(256)] per batch

// ---------------------------------------------------------------------------
// Helpers
// ---------------------------------------------------------------------------
static __device__ __forceinline__ void bsplit(float v, unsigned short& hi,
                                              unsigned short& lo) {
    __nv_bfloat16 h = __float2bfloat16(v);
    __nv_bfloat16 l = __float2bfloat16(v - __bfloat162float(h));
    hi = __bfloat16_as_ushort(h);
    lo = __bfloat16_as_ushort(l);
}

// D[16x8] += A[16x16] @ B[16x8], bf16 in, f32 accum (HMMA tensor pipe)
static __device__ __forceinline__ void mma_bf16(float* d, const uint32_t* a,
                                                uint32_t b0, uint32_t b1) {
    asm volatile(
        "mma.sync.aligned.m16n8k16.row.col.f32.bf16.bf16.f32 "
        "{%0,%1,%2,%3}, {%4,%5,%6,%7}, {%8,%9}, {%0,%1,%2,%3};"
        : "+f"(d[0]), "+f"(d[1]), "+f"(d[2]), "+f"(d[3])
        : "r"(a[0]), "r"(a[1]), "r"(a[2]), "r"(a[3]), "r"(b0), "r"(b1));
}

// ---------------------------------------------------------------------------
// Kernel 1: implicit-GEMM conv via mma.sync (3-term bf16 split) + bias/relu
//           + max/avg pool.  Grid: 512 CTAs = (batch, h-half). 8 warps.
//           Warp grid 4(M) x 2(N); warp tile 32(h) x 64(l).
// ---------------------------------------------------------------------------
__global__ void __launch_bounds__(256, 1)
conv_mma_kernel(const float* __restrict__ x, const float* __restrict__ wConv,
                const float* __restrict__ wRect) {
    extern __shared__ char smem[];
    const int tid   = threadIdx.x;
    const int lane  = tid & 31;
    const int wid   = tid >> 5;
    const int b     = blockIdx.x >> 1;
    const int hbase = (blockIdx.x & 1) * 128;
    const int wm    = wid & 3;        // warp M index (0..3)
    const int wn    = wid >> 2;       // warp N index (0..1)
    const int grp   = lane >> 2;      // 0..7
    const int tg    = lane & 3;       // 0..3
    const int kq    = tg * 2;

    unsigned long long* XiH = (unsigned long long*)(smem + OFF_XI_H);
    unsigned long long* XiL = (unsigned long long*)(smem + OFF_XI_L);
    float*              Wf  = (float*)(smem + OFF_WF);

    // ---- stage x[b]: interleaved bf16x4 hi/lo, zero-padded tail ----
    const float* xb = x + (size_t)b * 4 * LIN;
    for (int l = tid; l < XPAD; l += 256) {
        unsigned long long hv = 0ull, lv = 0ull;
        if (l < LIN) {
            unsigned short h0, l0, h1, l1, h2, l2, h3, l3;
            bsplit(xb[l],           h0, l0);
            bsplit(xb[LIN + l],     h1, l1);
            bsplit(xb[2 * LIN + l], h2, l2);
            bsplit(xb[3 * LIN + l], h3, l3);
            hv = (unsigned long long)h0 | ((unsigned long long)h1 << 16)
               | ((unsigned long long)h2 << 32) | ((unsigned long long)h3 << 48);
            lv = (unsigned long long)l0 | ((unsigned long long)l1 << 16)
               | ((unsigned long long)l2 << 32) | ((unsigned long long)l3 << 48);
        }
        XiH[l] = hv;  XiL[l] = lv;
    }

    // ---- stage this CTA's 128 weight rows as raw floats (coalesced) ----
    const float* wrow = wConv + (size_t)hbase * KDIM;
    for (int i = tid; i < 128 * KDIM; i += 256) Wf[i] = wrow[i];

    __syncthreads();

    // ---- A fragments in registers: [mtile][kstep][reg], hi & lo splits ----
    // reg layout (m16n8k16): r0: row grp, cols kq..kq+1 ; r1: row grp+8 ;
    //                        r2: row grp, cols +8       ; r3: row grp+8, +8
    uint32_t aH[2][6][4], aL[2][6][4];
#pragma unroll
    for (int mt = 0; mt < 2; ++mt)
#pragma unroll
        for (int ks = 0; ks < 6; ++ks)
#pragma unroll
            for (int rr = 0; rr < 4; ++rr) {
                int r  = wm * 32 + mt * 16 + grp + (rr & 1) * 8;
                int k0 = ks * 16 + kq + (rr >> 1) * 8;
                int k1 = k0 + 1;
                // k = 4g + c  ->  Wf index c*24 + g
                float f0 = Wf[r * KDIM + (k0 & 3) * GLEN + (k0 >> 2)];
                float f1 = Wf[r * KDIM + (k1 & 3) * GLEN + (k1 >> 2)];
                unsigned short h0, lo0, h1, lo1;
                bsplit(f0, h0, lo0);
                bsplit(f1, h1, lo1);
                aH[mt][ks][rr] = (uint32_t)h0  | ((uint32_t)h1  << 16);
                aL[mt][ks][rr] = (uint32_t)lo0 | ((uint32_t)lo1 << 16);
            }

    // per-thread bias values for the 4 h rows this thread owns
    float rb[2][2];
#pragma unroll
    for (int mt = 0; mt < 2; ++mt)
#pragma unroll
        for (int rh = 0; rh < 2; ++rh)
            rb[mt][rh] = wRect[hbase + wm * 32 + mt * 16 + rh * 8 + grp];

    float mx[2][2] = {{0.f, 0.f}, {0.f, 0.f}};   // rect >= 0 -> 0 is max identity
    float sm[2][2] = {{0.f, 0.f}, {0.f, 0.f}};

    // ------------------------------- main loop -------------------------------
    for (int t = 0; t < NTILES; ++t) {
        __syncthreads();              // prev tile's B reads done / Wf dead (t=0)

        // ---- build im2col B tile [n][k] (8B = one channel-quad per tap) ----
        const int l0 = t * 128;
#pragma unroll
        for (int i = 0; i < 12; ++i) {          // 12*256 = 128 rows * 24 taps
            int idx = i * 256 + tid;
            int lp  = idx & 127;
            int g   = idx >> 7;
            int doff = lp * (BPITCH * 2) + g * 8;
            *(unsigned long long*)(smem + OFF_BH + doff) = XiH[l0 + lp + g];
            *(unsigned long long*)(smem + OFF_BL + doff) = XiL[l0 + lp + g];
        }
        __syncthreads();

        // ---- 288 HMMAs: D[32x64] = A(128xK) @ B(K x 64) for this warp ----
        float d[2][8][4];
#pragma unroll
        for (int mt = 0; mt < 2; ++mt)
#pragma unroll
            for (int nt = 0; nt < 8; ++nt)
#pragma unroll
                for (int e = 0; e < 4; ++e) d[mt][nt][e] = 0.f;

#pragma unroll
        for (int ks = 0; ks < 6; ++ks) {
#pragma unroll
            for (int nt = 0; nt < 8; ++nt) {
                int n    = wn * 64 + nt * 8 + grp;
                int boff = n * (BPITCH * 2) + ks * 32 + kq * 2;
                uint32_t b0h = *(const uint32_t*)(smem + OFF_BH + boff);
                uint32_t b1h = *(const uint32_t*)(smem + OFF_BH + boff + 16);
                uint32_t b0l = *(const uint32_t*)(smem + OFF_BL + boff);
                uint32_t b1l = *(const uint32_t*)(smem + OFF_BL + boff + 16);
#pragma unroll
                for (int mt = 0; mt < 2; ++mt) {
                    mma_bf16(d[mt][nt], aH[mt][ks], b0h, b1h);
                    mma_bf16(d[mt][nt], aH[mt][ks], b0l, b1l);
                    mma_bf16(d[mt][nt], aL[mt][ks], b0h, b1h);
                }
            }
        }

        // ---- epilogue: bias + relu + masked max/sum (registers only) ----
        const int lb = t * 128 + wn * 64;
#pragma unroll
        for (int mt = 0; mt < 2; ++mt)
#pragma unroll
            for (int nt = 0; nt < 8; ++nt)
#pragma unroll
                for (int e = 0; e < 4; ++e) {
                    int rh = e >> 1;                      // row half (c2,c3 -> +8)
                    int n  = lb + nt * 8 + kq + (e & 1);  // output position
                    float r = fmaxf(d[mt][nt][e] + rb[mt][rh], 0.f);
                    if (n < LOUT) {
                        mx[mt][rh] = fmaxf(mx[mt][rh], r);
                        sm[mt][rh] += r;
                    }
                }
    }

    // ---- reduce across the 4 lanes sharing each h (lane%4 group) ----
    __syncthreads();                         // B buffers dead; reuse as scratch
    float* red = (float*)(smem + OFF_RED);   // [2(wn)][256? -> max|sum x 128] => 1024 floats
#pragma unroll
    for (int mt = 0; mt < 2; ++mt)
#pragma unroll
        for (int rh = 0; rh < 2; ++rh) {
            float mv = mx[mt][rh], sv = sm[mt][rh];
            mv = fmaxf(mv, __shfl_xor_sync(0xffffffffu, mv, 1));
            sv +=        __shfl_xor_sync(0xffffffffu, sv, 1);
            mv = fmaxf(mv, __shfl_xor_sync(0xffffffffu, mv, 2));
            sv +=        __shfl_xor_sync(0xffffffffu, sv, 2);
            if (tg == 0) {
                int m = wm * 32 + mt * 16 + rh * 8 + grp;
                red[wn * 128 + m]       = mv;
                red[256 + wn * 128 + m] = sv;
            }
        }
    __syncthreads();

    if (tid < 128) {
        float mv = fmaxf(red[tid], red[128 + tid]);
        float sv = red[256 + tid] + red[384 + tid];
        g_pool[b * TWOH + hbase + tid]         = mv;
        g_pool[b * TWOH + HNODE + hbase + tid] = sv * (1.0f / LOUT);
    }
}

// ---------------------------------------------------------------------------
// Kernel 2: MLP head (unchanged from passing baseline)
// ---------------------------------------------------------------------------
__global__ void __launch_bounds__(TWOH)
mlp_kernel(const float* __restrict__ wH, const float* __restrict__ wHB,
           const float* __restrict__ wNeu, const float* __restrict__ wNB,
           float* __restrict__ out) {
    __shared__ float prow[TWOH];
    __shared__ float red[TWOH];
    const int b = blockIdx.x, tid = threadIdx.x;

    prow[tid] = g_pool[b * TWOH + tid];
    __syncthreads();

    float acc = 0.0f;
#pragma unroll 8
    for (int i = 0; i < TWOH; ++i)
        acc = fmaf(prow[i], wH[i * TWOH + tid], acc);

    float hid = fmaxf(acc + wHB[tid], 0.0f);
    red[tid] = hid * wNeu[tid];
    __syncthreads();

#pragma unroll
    for (int st = TWOH / 2; st > 0; st >>= 1) {
        if (tid < st) red[tid] += red[tid + st];
        __syncthreads();
    }
    if (tid == 0) out[b] = 0.5f * red[0] + wNB[0];
}

// ---------------------------------------------------------------------------
// Launch
// ---------------------------------------------------------------------------
extern "C" void kernel_launch(void* const* d_in, const int* in_sizes, int n_in,
                              void* d_out, int out_size) {
    const float* x     = (const float*)d_in[0];
    const float* wConv = (const float*)d_in[1];
    const float* wRect = (const float*)d_in[2];
    const float* wH    = (const float*)d_in[3];
    const float* wHB   = (const float*)d_in[4];
    const float* wNeu  = (const float*)d_in[5];
    const float* wNB   = (const float*)d_in[6];
    float* out = (float*)d_out;

    static int smem_set = 0;
    if (!smem_set) {
        cudaFuncSetAttribute(conv_mma_kernel,
                             cudaFuncAttributeMaxDynamicSharedMemorySize,
                             SMEM_BYTES);
        smem_set = 1;
    }

    conv_mma_kernel<<<BATCH * 2, 256, SMEM_BYTES>>>(x, wConv, wRect);
    mlp_kernel<<<BATCH, TWOH>>>(wH, wHB, wNeu, wNB, out);
}

// round 4
// speedup vs baseline: 3.1807x; 1.1773x over previous
#include <cuda_runtime.h>
#include <cuda_bf16.h>
#include <cstdint>

// ---------------------------------------------------------------------------
// Problem constants
// ---------------------------------------------------------------------------
#define BATCH  256
#define LIN    2048
#define HNODE  256
#define GLEN   24
#define LOUT   2025
#define TWOH   512
#define KDIM   96            // 4 channels * 24 taps, k = 4*g + c
#define NTILES 16            // 16 * 128 l-positions
#define XPAD   2080          // max Xi word read = 1920+127+22+2 = 2071

// ---------------------------------------------------------------------------
// Shared memory layout (bytes)
// ---------------------------------------------------------------------------
#define OFF_XI_H 0                        // 2080 * 8 = 16640
#define OFF_XI_L 16640
#define OFF_WF   33280                    // prologue overlay: 128*96*4 = 49152
#define OFF_RED  33280                    // post-loop overlay: 1024 floats
#define SMEM_BYTES 82432

__device__ float g_pool[BATCH * TWOH];    // [max(256) | avg(256)] per batch
__device__ float g_part[BATCH * 2];       // per-(batch, o-half) head partials

// ---------------------------------------------------------------------------
// Helpers
// ---------------------------------------------------------------------------
static __device__ __forceinline__ void bsplit(float v, unsigned short& hi,
                                              unsigned short& lo) {
    __nv_bfloat16 h = __float2bfloat16(v);
    __nv_bfloat16 l = __float2bfloat16(v - __bfloat162float(h));
    hi = __bfloat16_as_ushort(h);
    lo = __bfloat16_as_ushort(l);
}

// D[16x8] += A[16x16] @ B[16x8], bf16 in, f32 accum (HMMA tensor pipe)
static __device__ __forceinline__ void mma_bf16(float* d, const uint32_t* a,
                                                uint32_t b0, uint32_t b1) {
    asm volatile(
        "mma.sync.aligned.m16n8k16.row.col.f32.bf16.bf16.f32 "
        "{%0,%1,%2,%3}, {%4,%5,%6,%7}, {%8,%9}, {%0,%1,%2,%3};"
        : "+f"(d[0]), "+f"(d[1]), "+f"(d[2]), "+f"(d[3])
        : "r"(a[0]), "r"(a[1]), "r"(a[2]), "r"(a[3]), "r"(b0), "r"(b1));
}

// ---------------------------------------------------------------------------
// Kernel 1: implicit-GEMM conv via mma.sync (3-term bf16 split).
// B fragments load DIRECTLY from the interleaved Xi image — no im2col build,
// no barriers in the main loop. Grid: 512 CTAs = (batch, h-half). 8 warps,
// warp grid 4(M) x 2(N); warp tile 32(h) x 64(l).
// ---------------------------------------------------------------------------
__global__ void __launch_bounds__(256, 1)
conv_mma_kernel(const float* __restrict__ x, const float* __restrict__ wConv,
                const float* __restrict__ wRect) {
    extern __shared__ char smem[];
    const int tid   = threadIdx.x;
    const int lane  = tid & 31;
    const int wid   = tid >> 5;
    const int b     = blockIdx.x >> 1;
    const int hbase = (blockIdx.x & 1) * 128;
    const int wm    = wid & 3;         // warp M index (0..3)
    const int wn    = wid >> 2;        // warp N index (0..1)
    const int grp   = lane >> 2;       // 0..7
    const int tg    = lane & 3;        // 0..3
    const int kq    = tg * 2;

    unsigned long long* XiH = (unsigned long long*)(smem + OFF_XI_H);
    unsigned long long* XiL = (unsigned long long*)(smem + OFF_XI_L);
    float*              Wf  = (float*)(smem + OFF_WF);

    // ---- stage x[b]: interleaved bf16x4 hi/lo, zero-padded tail ----
    const float* xb = x + (size_t)b * 4 * LIN;
    for (int l = tid; l < XPAD; l += 256) {
        unsigned long long hv = 0ull, lv = 0ull;
        if (l < LIN) {
            unsigned short h0, l0, h1, l1, h2, l2, h3, l3;
            bsplit(xb[l],           h0, l0);
            bsplit(xb[LIN + l],     h1, l1);
            bsplit(xb[2 * LIN + l], h2, l2);
            bsplit(xb[3 * LIN + l], h3, l3);
            hv = (unsigned long long)h0 | ((unsigned long long)h1 << 16)
               | ((unsigned long long)h2 << 32) | ((unsigned long long)h3 << 48);
            lv = (unsigned long long)l0 | ((unsigned long long)l1 << 16)
               | ((unsigned long long)l2 << 32) | ((unsigned long long)l3 << 48);
        }
        XiH[l] = hv;  XiL[l] = lv;
    }

    // ---- stage this CTA's 128 weight rows (coalesced), then A frags ----
    const float* wrow = wConv + (size_t)hbase * KDIM;
    for (int i = tid; i < 128 * KDIM; i += 256) Wf[i] = wrow[i];
    __syncthreads();

    uint32_t aH[2][6][4], aL[2][6][4];
#pragma unroll
    for (int mt = 0; mt < 2; ++mt)
#pragma unroll
        for (int ks = 0; ks < 6; ++ks)
#pragma unroll
            for (int rr = 0; rr < 4; ++rr) {
                int r  = wm * 32 + mt * 16 + grp + (rr & 1) * 8;
                int k0 = ks * 16 + kq + (rr >> 1) * 8;
                int k1 = k0 + 1;
                float f0 = Wf[r * KDIM + (k0 & 3) * GLEN + (k0 >> 2)];
                float f1 = Wf[r * KDIM + (k1 & 3) * GLEN + (k1 >> 2)];
                unsigned short h0, lo0, h1, lo1;
                bsplit(f0, h0, lo0);
                bsplit(f1, h1, lo1);
                aH[mt][ks][rr] = (uint32_t)h0  | ((uint32_t)h1  << 16);
                aL[mt][ks][rr] = (uint32_t)lo0 | ((uint32_t)lo1 << 16);
            }

    float rb[2][2];
#pragma unroll
    for (int mt = 0; mt < 2; ++mt)
#pragma unroll
        for (int rh = 0; rh < 2; ++rh)
            rb[mt][rh] = wRect[hbase + wm * 32 + mt * 16 + rh * 8 + grp];

    __syncthreads();   // Wf dead after this; warps run free from here on

    // b-fragment base (in 32-bit words within XiH/XiL):
    //   word(ks,nt,l0) = 2*(l0 + n + 4ks + (tg>>1)) + (tg&1),  n = wn*64+nt*8+grp
    const uint32_t* XiHw = (const uint32_t*)(smem + OFF_XI_H);
    const uint32_t* XiLw = (const uint32_t*)(smem + OFF_XI_L);
    const int tbase = 2 * (wn * 64 + grp + (tg >> 1)) + (tg & 1);

    float mx[2][2] = {{0.f, 0.f}, {0.f, 0.f}};
    float sm[2][2] = {{0.f, 0.f}, {0.f, 0.f}};

    for (int t = 0; t < NTILES; ++t) {
        const int base_t = tbase + 2 * t * 128;

        float d[2][8][4];
#pragma unroll
        for (int mt = 0; mt < 2; ++mt)
#pragma unroll
            for (int nt = 0; nt < 8; ++nt)
#pragma unroll
                for (int e = 0; e < 4; ++e) d[mt][nt][e] = 0.f;

#pragma unroll
        for (int ks = 0; ks < 6; ++ks) {
#pragma unroll
            for (int nt = 0; nt < 8; ++nt) {
                const int w0 = base_t + 2 * (nt * 8 + 4 * ks);
                uint32_t b0h = XiHw[w0];
                uint32_t b1h = XiHw[w0 + 4];
                uint32_t b0l = XiLw[w0];
                uint32_t b1l = XiLw[w0 + 4];
#pragma unroll
                for (int mt = 0; mt < 2; ++mt) {
                    mma_bf16(d[mt][nt], aH[mt][ks], b0h, b1h);
                    mma_bf16(d[mt][nt], aH[mt][ks], b0l, b1l);
                    mma_bf16(d[mt][nt], aL[mt][ks], b0h, b1h);
                }
            }
        }

        // ---- epilogue: bias + relu + max/sum; mask only on the last tile ----
        if (t < NTILES - 1) {
#pragma unroll
            for (int mt = 0; mt < 2; ++mt)
#pragma unroll
                for (int nt = 0; nt < 8; ++nt)
#pragma unroll
                    for (int e = 0; e < 4; ++e) {
                        int rh = e >> 1;
                        float r = fmaxf(d[mt][nt][e] + rb[mt][rh], 0.f);
                        mx[mt][rh] = fmaxf(mx[mt][rh], r);
                        sm[mt][rh] += r;
                    }
        } else {
            const int lb = t * 128 + wn * 64;
#pragma unroll
            for (int mt = 0; mt < 2; ++mt)
#pragma unroll
                for (int nt = 0; nt < 8; ++nt)
#pragma unroll
                    for (int e = 0; e < 4; ++e) {
                        int rh = e >> 1;
                        int n  = lb + nt * 8 + kq + (e & 1);
                        float r = fmaxf(d[mt][nt][e] + rb[mt][rh], 0.f);
                        if (n < LOUT) {
                            mx[mt][rh] = fmaxf(mx[mt][rh], r);
                            sm[mt][rh] += r;
                        }
                    }
        }
    }

    // ---- reduce across the 4 lanes sharing each h; then across wn ----
    __syncthreads();                          // Xi reads done; overlay scratch
    float* red = (float*)(smem + OFF_RED);    // 1024 floats
#pragma unroll
    for (int mt = 0; mt < 2; ++mt)
#pragma unroll
        for (int rh = 0; rh < 2; ++rh) {
            float mv = mx[mt][rh], sv = sm[mt][rh];
            mv = fmaxf(mv, __shfl_xor_sync(0xffffffffu, mv, 1));
            sv +=        __shfl_xor_sync(0xffffffffu, sv, 1);
            mv = fmaxf(mv, __shfl_xor_sync(0xffffffffu, mv, 2));
            sv +=        __shfl_xor_sync(0xffffffffu, sv, 2);
            if (tg == 0) {
                int m = wm * 32 + mt * 16 + rh * 8 + grp;
                red[wn * 128 + m]       = mv;
                red[256 + wn * 128 + m] = sv;
            }
        }
    __syncthreads();

    if (tid < 128) {
        float mv = fmaxf(red[tid], red[128 + tid]);
        float sv = red[256 + tid] + red[384 + tid];
        g_pool[b * TWOH + hbase + tid]         = mv;
        g_pool[b * TWOH + HNODE + hbase + tid] = sv * (1.0f / LOUT);
    }
}

// ---------------------------------------------------------------------------
// Kernel 2: MLP head, batched GEMV. Grid 128 = (64 batch-quads x 2 o-halves),
// 256 threads. Each CTA: 4 batches x 256 outputs; pool transposed to float4.
// Writes per-(batch, o-half) partial dot products with wNeu.
// ---------------------------------------------------------------------------
__global__ void __launch_bounds__(256)
mlp_kernel(const float* __restrict__ wH, const float* __restrict__ wHB,
           const float* __restrict__ wNeu) {
    __shared__ float4 prow[TWOH];     // prow[i] = pool[b0..b0+3][i]
    __shared__ float  redsm[32];

    const int tid = threadIdx.x;
    const int bt  = blockIdx.x >> 1;           // batch quad
    const int oh  = blockIdx.x & 1;            // output half
    const int o   = oh * 256 + tid;
    const int b0  = bt * 4;

    for (int i = tid; i < TWOH; i += 256) {
        float4 v;
        v.x = g_pool[(b0 + 0) * TWOH + i];
        v.y = g_pool[(b0 + 1) * TWOH + i];
        v.z = g_pool[(b0 + 2) * TWOH + i];
        v.w = g_pool[(b0 + 3) * TWOH + i];
        prow[i] = v;
    }
    __syncthreads();

    float a0 = 0.f, a1 = 0.f, a2 = 0.f, a3 = 0.f;
#pragma unroll 8
    for (int i = 0; i < TWOH; ++i) {
        float w = wH[i * TWOH + o];
        float4 p = prow[i];
        a0 = fmaf(p.x, w, a0);
        a1 = fmaf(p.y, w, a1);
        a2 = fmaf(p.z, w, a2);
        a3 = fmaf(p.w, w, a3);
    }

    const float hb = wHB[o];
    const float wv = wNeu[o];
    float vals[4];
    vals[0] = fmaxf(a0 + hb, 0.f) * wv;
    vals[1] = fmaxf(a1 + hb, 0.f) * wv;
    vals[2] = fmaxf(a2 + hb, 0.f) * wv;
    vals[3] = fmaxf(a3 + hb, 0.f) * wv;

    const int lane = tid & 31, wid = tid >> 5;
#pragma unroll
    for (int j = 0; j < 4; ++j) {
        float v = vals[j];
        v += __shfl_xor_sync(0xffffffffu, v, 16);
        v += __shfl_xor_sync(0xffffffffu, v, 8);
        v += __shfl_xor_sync(0xffffffffu, v, 4);
        v += __shfl_xor_sync(0xffffffffu, v, 2);
        v += __shfl_xor_sync(0xffffffffu, v, 1);
        if (lane == 0) redsm[j * 8 + wid] = v;
    }
    __syncthreads();

    if (tid < 32) {
        float v = redsm[tid];
        v += __shfl_xor_sync(0xffffffffu, v, 4);
        v += __shfl_xor_sync(0xffffffffu, v, 2);
        v += __shfl_xor_sync(0xffffffffu, v, 1);
        if ((tid & 7) == 0)
            g_part[(b0 + (tid >> 3)) * 2 + oh] = v;
    }
}

// ---------------------------------------------------------------------------
// Kernel 3: combine partials -> out[b] = 0.5*(p0+p1) + wNeuBias
// ---------------------------------------------------------------------------
__global__ void __launch_bounds__(256)
final_kernel(const float* __restrict__ wNB, float* __restrict__ out) {
    int b = threadIdx.x;
    out[b] = 0.5f * (g_part[2 * b] + g_part[2 * b + 1]) + wNB[0];
}

// ---------------------------------------------------------------------------
// Launch
// ---------------------------------------------------------------------------
extern "C" void kernel_launch(void* const* d_in, const int* in_sizes, int n_in,
                              void* d_out, int out_size) {
    const float* x     = (const float*)d_in[0];
    const float* wConv = (const float*)d_in[1];
    const float* wRect = (const float*)d_in[2];
    const float* wH    = (const float*)d_in[3];
    const float* wHB   = (const float*)d_in[4];
    const float* wNeu  = (const float*)d_in[5];
    const float* wNB   = (const float*)d_in[6];
    float* out = (float*)d_out;

    static int smem_set = 0;
    if (!smem_set) {
        cudaFuncSetAttribute(conv_mma_kernel,
                             cudaFuncAttributeMaxDynamicSharedMemorySize,
                             SMEM_BYTES);
        smem_set = 1;
    }

    conv_mma_kernel<<<BATCH * 2, 256, SMEM_BYTES>>>(x, wConv, wRect);
    mlp_kernel<<<128, 256>>>(wH, wHB, wNeu);
    final_kernel<<<1, 256>>>(wNB, out);
}

// round 5
// speedup vs baseline: 3.2990x; 1.0372x over previous
#include <cuda_runtime.h>
#include <cuda_bf16.h>
#include <cstdint>

// ---------------------------------------------------------------------------
// Problem constants
// ---------------------------------------------------------------------------
#define BATCH  256
#define LIN    2048
#define HNODE  256
#define GLEN   24
#define LOUT   2025
#define TWOH   512
#define KDIM   96
#define NTLOC  8             // tiles of 128 l-positions per CTA (l-half)
#define NLOC   1056          // staged local positions (1024 + 23 + pad)
#define NQ     2096          // XiQ slots: 2*1048

// ---------------------------------------------------------------------------
// Shared memory layout (bytes)
// ---------------------------------------------------------------------------
#define OFF_XIQ  0                       // 2096 * 16 = 33536
#define OFF_TH   33536                   // 1056 * 8  = 8448
#define OFF_TL   41984                   // 8448 -> 50432
#define OFF_RED  33536                   // overlay (TH dead): 1024 floats
#define SMEM_BYTES 50432

__device__ float g_pp[BATCH * 2 * TWOH];  // per (b, l-half): [max | unscaled sum]
__device__ float g_part[BATCH * 2];       // per (batch, o-half) head partials

// ---------------------------------------------------------------------------
// Helpers
// ---------------------------------------------------------------------------
static __device__ __forceinline__ void bsplit(float v, unsigned short& hi,
                                              unsigned short& lo) {
    __nv_bfloat16 h = __float2bfloat16(v);
    __nv_bfloat16 l = __float2bfloat16(v - __bfloat162float(h));
    hi = __bfloat16_as_ushort(h);
    lo = __bfloat16_as_ushort(l);
}

static __device__ __forceinline__ void mma_bf16(float* d, const uint32_t* a,
                                                uint32_t b0, uint32_t b1) {
    asm volatile(
        "mma.sync.aligned.m16n8k16.row.col.f32.bf16.bf16.f32 "
        "{%0,%1,%2,%3}, {%4,%5,%6,%7}, {%8,%9}, {%0,%1,%2,%3};"
        : "+f"(d[0]), "+f"(d[1]), "+f"(d[2]), "+f"(d[3])
        : "r"(a[0]), "r"(a[1]), "r"(a[2]), "r"(a[3]), "r"(b0), "r"(b1));
}

// ---------------------------------------------------------------------------
// Kernel 1: implicit-GEMM conv, 3-term bf16 split, packed 16B b-fragments.
// Grid: 1024 CTAs = (batch, h-half, l-half). 8 warps, warp grid 4(M) x 2(N),
// warp tile 32(h) x 64(l). 8 n-tiles of 128 per CTA. No main-loop barriers.
// ---------------------------------------------------------------------------
__global__ void __launch_bounds__(256, 1)
conv_mma_kernel(const float* __restrict__ x, const float* __restrict__ wConv,
                const float* __restrict__ wRect) {
    extern __shared__ char smem[];
    const int tid   = threadIdx.x;
    const int lane  = tid & 31;
    const int wid   = tid >> 5;
    const int b     = blockIdx.x >> 2;
    const int mh    = (blockIdx.x >> 1) & 1;
    const int lq    = blockIdx.x & 1;
    const int hbase = mh * 128;
    const int L0    = lq * 1024;
    const int wm    = wid & 3;
    const int wn    = wid >> 2;
    const int grp   = lane >> 2;
    const int tg    = lane & 3;
    const int kq    = tg * 2;

    unsigned long long* TH = (unsigned long long*)(smem + OFF_TH);
    unsigned long long* TL = (unsigned long long*)(smem + OFF_TL);

    // ---- phase 1: stage local x slice, interleaved bf16x4 hi/lo ----
    const float* xb = x + (size_t)b * 4 * LIN;
    for (int l = tid; l < NLOC; l += 256) {
        const int gl = L0 + l;
        unsigned long long hv = 0ull, lv = 0ull;
        if (gl < LIN) {
            unsigned short h0, l0, h1, l1, h2, l2, h3, l3;
            bsplit(xb[gl],           h0, l0);
            bsplit(xb[LIN + gl],     h1, l1);
            bsplit(xb[2 * LIN + gl], h2, l2);
            bsplit(xb[3 * LIN + gl], h3, l3);
            hv = (unsigned long long)h0 | ((unsigned long long)h1 << 16)
               | ((unsigned long long)h2 << 32) | ((unsigned long long)h3 << 48);
            lv = (unsigned long long)l0 | ((unsigned long long)l1 << 16)
               | ((unsigned long long)l2 << 32) | ((unsigned long long)l3 << 48);
        }
        TH[l] = hv;  TL[l] = lv;
    }
    __syncthreads();

    // ---- phase 2: build packed XiQ. slot(2l+p) = {b0h,b1h,b0l,b1l} ----
    {
        const uint32_t* THw = (const uint32_t*)TH;
        const uint32_t* TLw = (const uint32_t*)TL;
        uint4* XiQ = (uint4*)(smem + OFF_XIQ);
        for (int i = tid; i < NQ; i += 256) {
            const int w = i;            // = 2l + p
            uint4 q;
            q.x = THw[w];       q.y = THw[w + 4];
            q.z = TLw[w];       q.w = TLw[w + 4];
            XiQ[i] = q;
        }
    }

    // ---- A fragments straight from gmem (wConv is L2-resident) ----
    uint32_t aH[2][6][4], aL[2][6][4];
#pragma unroll
    for (int mt = 0; mt < 2; ++mt)
#pragma unroll
        for (int ks = 0; ks < 6; ++ks)
#pragma unroll
            for (int rr = 0; rr < 4; ++rr) {
                const int r  = wm * 32 + mt * 16 + grp + (rr & 1) * 8;
                const int k0 = ks * 16 + kq + (rr >> 1) * 8;      // even
                const int base = (hbase + r) * KDIM + (k0 >> 2);
                const float f0 = wConv[base + (k0 & 3) * GLEN];
                const float f1 = wConv[base + ((k0 & 3) + 1) * GLEN];
                unsigned short h0, lo0, h1, lo1;
                bsplit(f0, h0, lo0);
                bsplit(f1, h1, lo1);
                aH[mt][ks][rr] = (uint32_t)h0  | ((uint32_t)h1  << 16);
                aL[mt][ks][rr] = (uint32_t)lo0 | ((uint32_t)lo1 << 16);
            }

    float rb[2][2];
#pragma unroll
    for (int mt = 0; mt < 2; ++mt)
#pragma unroll
        for (int rh = 0; rh < 2; ++rh)
            rb[mt][rh] = wRect[hbase + wm * 32 + mt * 16 + rh * 8 + grp];

    __syncthreads();

    const uint4* XiQ = (const uint4*)(smem + OFF_XIQ);
    // slot = 2*(tloc*128 + n + 4ks + (tg>>1)) + (tg&1), n = wn*64 + nt*8 + grp
    const int sbase = 2 * (wn * 64 + grp + (tg >> 1)) + (tg & 1);

    float mx[2][2] = {{0.f, 0.f}, {0.f, 0.f}};
    float sm[2][2] = {{0.f, 0.f}, {0.f, 0.f}};
    const bool hasMask = (lq == 1);

    for (int t = 0; t < NTLOC; ++t) {
        const int base_t = sbase + 2 * t * 128;

        float d[2][8][4];
#pragma unroll
        for (int mt = 0; mt < 2; ++mt)
#pragma unroll
            for (int nt = 0; nt < 8; ++nt)
#pragma unroll
                for (int e = 0; e < 4; ++e) d[mt][nt][e] = 0.f;

#pragma unroll
        for (int ks = 0; ks < 6; ++ks) {
#pragma unroll
            for (int nt = 0; nt < 8; ++nt) {
                const uint4 q = XiQ[base_t + 2 * (nt * 8 + 4 * ks)];
#pragma unroll
                for (int mt = 0; mt < 2; ++mt) {
                    mma_bf16(d[mt][nt], aH[mt][ks], q.x, q.y);
                    mma_bf16(d[mt][nt], aH[mt][ks], q.z, q.w);
                    mma_bf16(d[mt][nt], aL[mt][ks], q.x, q.y);
                }
            }
        }

        if (!(hasMask && t == NTLOC - 1)) {
#pragma unroll
            for (int mt = 0; mt < 2; ++mt)
#pragma unroll
                for (int nt = 0; nt < 8; ++nt)
#pragma unroll
                    for (int e = 0; e < 4; ++e) {
                        const int rh = e >> 1;
                        float r = fmaxf(d[mt][nt][e] + rb[mt][rh], 0.f);
                        mx[mt][rh] = fmaxf(mx[mt][rh], r);
                        sm[mt][rh] += r;
                    }
        } else {
            const int lb = L0 + t * 128 + wn * 64;
#pragma unroll
            for (int mt = 0; mt < 2; ++mt)
#pragma unroll
                for (int nt = 0; nt < 8; ++nt)
#pragma unroll
                    for (int e = 0; e < 4; ++e) {
                        const int rh = e >> 1;
                        const int n  = lb + nt * 8 + kq + (e & 1);
                        float r = fmaxf(d[mt][nt][e] + rb[mt][rh], 0.f);
                        if (n < LOUT) {
                            mx[mt][rh] = fmaxf(mx[mt][rh], r);
                            sm[mt][rh] += r;
                        }
                    }
        }
    }

    // ---- lane-group reduce, then cross-wn combine, write partials ----
    __syncthreads();
    float* red = (float*)(smem + OFF_RED);
#pragma unroll
    for (int mt = 0; mt < 2; ++mt)
#pragma unroll
        for (int rh = 0; rh < 2; ++rh) {
            float mv = mx[mt][rh], sv = sm[mt][rh];
            mv = fmaxf(mv, __shfl_xor_sync(0xffffffffu, mv, 1));
            sv +=        __shfl_xor_sync(0xffffffffu, sv, 1);
            mv = fmaxf(mv, __shfl_xor_sync(0xffffffffu, mv, 2));
            sv +=        __shfl_xor_sync(0xffffffffu, sv, 2);
            if (tg == 0) {
                const int m = wm * 32 + mt * 16 + rh * 8 + grp;
                red[wn * 128 + m]       = mv;
                red[256 + wn * 128 + m] = sv;
            }
        }
    __syncthreads();

    if (tid < 128) {
        const float mv = fmaxf(red[tid], red[128 + tid]);
        const float sv = red[256 + tid] + red[384 + tid];
        float* pp = g_pp + (size_t)(b * 2 + lq) * TWOH;
        pp[hbase + tid]         = mv;
        pp[HNODE + hbase + tid] = sv;     // unscaled sum
    }
}

// ---------------------------------------------------------------------------
// Kernel 2: MLP head, batched GEMV with partial-pool combine in staging.
// Grid 128 = (64 batch-quads x 2 o-halves), 256 threads.
// ---------------------------------------------------------------------------
__global__ void __launch_bounds__(256)
mlp_kernel(const float* __restrict__ wH, const float* __restrict__ wHB,
           const float* __restrict__ wNeu) {
    __shared__ float4 prow[TWOH];
    __shared__ float  redsm[32];

    const int tid = threadIdx.x;
    const int bt  = blockIdx.x >> 1;
    const int oh  = blockIdx.x & 1;
    const int o   = oh * 256 + tid;
    const int b0  = bt * 4;

    for (int i = tid; i < TWOH; i += 256) {
        float4 v;
        const float inv = 1.0f / LOUT;
#pragma unroll
        for (int j = 0; j < 4; ++j) {
            const float* p0 = g_pp + (size_t)((b0 + j) * 2 + 0) * TWOH;
            const float* p1 = g_pp + (size_t)((b0 + j) * 2 + 1) * TWOH;
            float val = (i < HNODE) ? fmaxf(p0[i], p1[i])
                                    : (p0[i] + p1[i]) * inv;
            ((float*)&v)[j] = val;
        }
        prow[i] = v;
    }
    __syncthreads();

    float a0 = 0.f, a1 = 0.f, a2 = 0.f, a3 = 0.f;
#pragma unroll 8
    for (int i = 0; i < TWOH; ++i) {
        const float w = wH[i * TWOH + o];
        const float4 p = prow[i];
        a0 = fmaf(p.x, w, a0);
        a1 = fmaf(p.y, w, a1);
        a2 = fmaf(p.z, w, a2);
        a3 = fmaf(p.w, w, a3);
    }

    const float hb = wHB[o];
    const float wv = wNeu[o];
    float vals[4];
    vals[0] = fmaxf(a0 + hb, 0.f) * wv;
    vals[1] = fmaxf(a1 + hb, 0.f) * wv;
    vals[2] = fmaxf(a2 + hb, 0.f) * wv;
    vals[3] = fmaxf(a3 + hb, 0.f) * wv;

    const int lane = tid & 31, wid = tid >> 5;
#pragma unroll
    for (int j = 0; j < 4; ++j) {
        float v = vals[j];
        v += __shfl_xor_sync(0xffffffffu, v, 16);
        v += __shfl_xor_sync(0xffffffffu, v, 8);
        v += __shfl_xor_sync(0xffffffffu, v, 4);
        v += __shfl_xor_sync(0xffffffffu, v, 2);
        v += __shfl_xor_sync(0xffffffffu, v, 1);
        if (lane == 0) redsm[j * 8 + wid] = v;
    }
    __syncthreads();

    if (tid < 32) {
        float v = redsm[tid];
        v += __shfl_xor_sync(0xffffffffu, v, 4);
        v += __shfl_xor_sync(0xffffffffu, v, 2);
        v += __shfl_xor_sync(0xffffffffu, v, 1);
        if ((tid & 7) == 0)
            g_part[(b0 + (tid >> 3)) * 2 + oh] = v;
    }
}

// ---------------------------------------------------------------------------
// Kernel 3: out[b] = 0.5*(p0+p1) + wNeuBias
// ---------------------------------------------------------------------------
__global__ void __launch_bounds__(256)
final_kernel(const float* __restrict__ wNB, float* __restrict__ out) {
    const int b = threadIdx.x;
    out[b] = 0.5f * (g_part[2 * b] + g_part[2 * b + 1]) + wNB[0];
}

// ---------------------------------------------------------------------------
// Launch
// ---------------------------------------------------------------------------
extern "C" void kernel_launch(void* const* d_in, const int* in_sizes, int n_in,
                              void* d_out, int out_size) {
    const float* x     = (const float*)d_in[0];
    const float* wConv = (const float*)d_in[1];
    const float* wRect = (const float*)d_in[2];
    const float* wH    = (const float*)d_in[3];
    const float* wHB   = (const float*)d_in[4];
    const float* wNeu  = (const float*)d_in[5];
    const float* wNB   = (const float*)d_in[6];
    float* out = (float*)d_out;

    static int smem_set = 0;
    if (!smem_set) {
        cudaFuncSetAttribute(conv_mma_kernel,
                             cudaFuncAttributeMaxDynamicSharedMemorySize,
                             SMEM_BYTES);
        smem_set = 1;
    }

    conv_mma_kernel<<<BATCH * 4, 256, SMEM_BYTES>>>(x, wConv, wRect);
    mlp_kernel<<<128, 256>>>(wH, wHB, wNeu);
    final_kernel<<<1, 256>>>(wNB, out);
}